// round 1
// baseline (speedup 1.0000x reference)
#include <cuda_runtime.h>
#include <math.h>

#define BB 16
#define AA 3
#define CC 80
#define HH 76
#define WW 76
#define TT 50
#define HWW (HH*WW)           /* 5776 */
#define NCELL (BB*AA*HWW)     /* 277248 */
#define NCH (5+CC)            /* 85 */
#define SCAN_BLOCKS 512
#define SCAN_THREADS 256

// ---------------- device scratch (no allocations allowed) ----------------
__device__ unsigned char g_noobj[NCELL];
__device__ int g_nentries;
__device__ int g_ecell[BB*TT];
__device__ float g_etx[BB*TT], g_ety[BB*TT], g_etw[BB*TT], g_eth[BB*TT];
__device__ unsigned int g_ecls[BB*TT][3];
__device__ double g_psum[SCAN_BLOCKS], g_pcnt[SCAN_BLOCKS];
__device__ double g_acc[6];   // bx, by, sqw, sqh, bconf_masked, bcls

// ---------------- kernel 0: init flags + accumulators ----------------
__global__ void k_init() {
    int tid = blockIdx.x * blockDim.x + threadIdx.x;
    int stride = gridDim.x * blockDim.x;
    for (int i = tid; i < NCELL; i += stride) g_noobj[i] = 1;
    if (tid < 6) g_acc[tid] = 0.0;
    if (tid == 6) g_nentries = 0;
}

// ---------------- kernel 1: build targets (scatter with last-writer-wins) ----
__global__ void k_build(const float* __restrict__ tgt) {
    __shared__ float st[BB*TT*5];
    for (int i = threadIdx.x; i < BB*TT*5; i += blockDim.x) st[i] = tgt[i];
    __syncthreads();
    int b = threadIdx.x;
    if (b >= BB) return;

    const float aw[3] = {1.25f, 2.0f, 4.125f};     // ANCHORS / STRIDE (stride = 8)
    const float ah[3] = {1.625f, 3.75f, 2.875f};

    int cells[TT];
    float ltx[TT], lty[TT], ltw[TT], lth[TT];
    unsigned int cm[TT][3];
    int cnt = 0;

    for (int t = 0; t < TT; t++) {
        const float* p = &st[(b*TT + t)*5];
        float cls = p[0], x = p[1], y = p[2], w = p[3], h = p[4];
        bool valid = (cls + x + y + w + h) != 0.0f;
        if (!valid) continue;
        float gx = x * WW, gy = y * HH, gw = w * WW, gh = h * HH;
        int gi = (int)gx, gj = (int)gy;
        float a1 = (gw + 1.0f) * (gh + 1.0f);
        float biou = -1.0f; int best = 0;
        bool inb = (gj >= 0) && (gj < HH) && (gi >= 0) && (gi < WW);
        #pragma unroll
        for (int a = 0; a < 3; a++) {
            float inter = fmaxf(fminf(gw, aw[a]) + 1.0f, 0.0f) *
                          fmaxf(fminf(gh, ah[a]) + 1.0f, 0.0f);
            float a2 = (aw[a] + 1.0f) * (ah[a] + 1.0f);
            float iou = inter / (a1 + a2 - inter + 1e-16f);
            if (iou > biou) { biou = iou; best = a; }
            if (iou > 0.5f && inb)
                g_noobj[((b*AA + a)*HH + gj)*WW + gi] = 0;
        }
        if (inb) {  // ok
            int cell = ((b*AA + best)*HH + gj)*WW + gi;
            float tx = gx - (float)gi, ty = gy - (float)gj;
            float tw = logf(gw / aw[best] + 1e-16f);
            float th = logf(gh / ah[best] + 1e-16f);
            int ci = (int)cls;
            int j = -1;
            for (int k = 0; k < cnt; k++) if (cells[k] == cell) { j = k; break; }
            if (j < 0) { j = cnt++; cells[j] = cell; cm[j][0] = cm[j][1] = cm[j][2] = 0u; }
            ltx[j] = tx; lty[j] = ty; ltw[j] = tw; lth[j] = th;  // last writer wins
            cm[j][ci >> 5] |= (1u << (ci & 31));                 // tcls: OR of all writers
        }
    }
    int off = atomicAdd(&g_nentries, cnt);
    for (int k = 0; k < cnt; k++) {
        g_ecell[off+k] = cells[k];
        g_etx[off+k] = ltx[k]; g_ety[off+k] = lty[k];
        g_etw[off+k] = ltw[k]; g_eth[off+k] = lth[k];
        g_ecls[off+k][0] = cm[k][0]; g_ecls[off+k][1] = cm[k][1]; g_ecls[off+k][2] = cm[k][2];
    }
}

// ---------------- kernel 2: noobj conf scan (the only full-grid pass) --------
__global__ void k_scan(const float* __restrict__ inp) {
    __shared__ double ss[SCAN_THREADS], sc[SCAN_THREADS];
    double s = 0.0, c = 0.0;
    int stride = gridDim.x * blockDim.x;
    for (int i = blockIdx.x * blockDim.x + threadIdx.x; i < NCELL; i += stride) {
        if (g_noobj[i]) {
            int b = i / (AA*HWW);
            int r = i - b*(AA*HWW);
            int a = r / HWW;
            int hw = r - a*HWW;
            float l = inp[(size_t)b*(NCH*AA)*HWW + (size_t)(a*NCH + 4)*HWW + hw];
            float p = 1.0f / (1.0f + expf(-l));
            float term = -fmaxf(logf(1.0f - p), -100.0f);   // bce(conf, 0)
            s += (double)term; c += 1.0;
        }
    }
    ss[threadIdx.x] = s; sc[threadIdx.x] = c;
    __syncthreads();
    for (int o = SCAN_THREADS >> 1; o > 0; o >>= 1) {
        if (threadIdx.x < o) { ss[threadIdx.x] += ss[threadIdx.x+o]; sc[threadIdx.x] += sc[threadIdx.x+o]; }
        __syncthreads();
    }
    if (threadIdx.x == 0) { g_psum[blockIdx.x] = ss[0]; g_pcnt[blockIdx.x] = sc[0]; }
}

// ---------------- kernel 3: masked-cell losses (one warp per cell) ----------
__device__ __forceinline__ float bcef(float l, float t) {
    float p = 1.0f / (1.0f + expf(-l));
    float lp  = fmaxf(logf(p), -100.0f);
    float l1p = fmaxf(logf(1.0f - p), -100.0f);
    return -(t * lp + (1.0f - t) * l1p);
}

__global__ void k_masked(const float* __restrict__ inp) {
    int wid  = (blockIdx.x * blockDim.x + threadIdx.x) >> 5;
    int lane = threadIdx.x & 31;
    int nw   = (gridDim.x * blockDim.x) >> 5;
    int nE   = g_nentries;
    double a0 = 0, a1 = 0, a2 = 0, a3 = 0, a4 = 0, a5 = 0;
    for (int e = wid; e < nE; e += nw) {
        int cell = g_ecell[e];
        int b = cell / (AA*HWW);
        int r = cell - b*(AA*HWW);
        int a = r / HWW;
        int hw = r - a*HWW;
        size_t base = (size_t)b*(NCH*AA)*HWW + (size_t)(a*NCH)*HWW + hw;
        unsigned int m0 = g_ecls[e][0], m1 = g_ecls[e][1], m2 = g_ecls[e][2];
        float cs = 0.0f;
        #pragma unroll
        for (int cc = 0; cc < 3; cc++) {
            int c = lane + cc * 32;
            if (c < CC) {
                float l = inp[base + (size_t)(5 + c) * HWW];
                unsigned int mm = (c < 32) ? m0 : ((c < 64) ? m1 : m2);
                float t = ((mm >> (c & 31)) & 1u) ? 1.0f : 0.0f;
                cs += bcef(l, t);
            }
        }
        #pragma unroll
        for (int o = 16; o > 0; o >>= 1) cs += __shfl_down_sync(0xffffffffu, cs, o);
        if (lane == 0) {
            float l0 = inp[base];
            float l1 = inp[base + HWW];
            float l2 = inp[base + 2*HWW];
            float l3 = inp[base + 3*HWW];
            float l4 = inp[base + 4*HWW];
            a0 += (double)bcef(l0, g_etx[e]);
            a1 += (double)bcef(l1, g_ety[e]);
            float dw = l2 - g_etw[e], dh = l3 - g_eth[e];
            a2 += (double)(dw * dw);
            a3 += (double)(dh * dh);
            a4 += (double)bcef(l4, 1.0f);     // bce(conf, 1)
            a5 += (double)cs;
        }
    }
    if (lane == 0) {
        atomicAdd(&g_acc[0], a0); atomicAdd(&g_acc[1], a1);
        atomicAdd(&g_acc[2], a2); atomicAdd(&g_acc[3], a3);
        atomicAdd(&g_acc[4], a4); atomicAdd(&g_acc[5], a5);
    }
}

// ---------------- kernel 4: final combine ----------------
__global__ void k_final(float* __restrict__ out) {
    __shared__ double ss[SCAN_BLOCKS], sc[SCAN_BLOCKS];
    int tid = threadIdx.x;
    ss[tid] = g_psum[tid]; sc[tid] = g_pcnt[tid];
    __syncthreads();
    for (int o = SCAN_BLOCKS >> 1; o > 0; o >>= 1) {
        if (tid < o) { ss[tid] += ss[tid+o]; sc[tid] += sc[tid+o]; }
        __syncthreads();
    }
    if (tid == 0) {
        double Nd   = (double)NCELL;
        double n_m  = (double)g_nentries;
        double n_nm = sc[0];
        double lx = (g_acc[0] / Nd) / n_m;
        double ly = (g_acc[1] / Nd) / n_m;
        double lw = (g_acc[2] / Nd) / n_m;
        double lh = (g_acc[3] / Nd) / n_m;
        double lconf = (g_acc[4] / Nd) / n_m + 0.5 * (ss[0] / Nd) / n_nm;
        double lcls  = g_acc[5] / (n_m * (double)CC) / n_m;
        double loss  = 2.5 * (lx + ly) + 2.5 * (lw + lh) + lconf + lcls;
        out[0] = (float)loss;
        out[1] = (float)lx;  out[2] = (float)ly;
        out[3] = (float)lw;  out[4] = (float)lh;
        out[5] = (float)lconf; out[6] = (float)lcls;
    }
}

// ---------------- launch ----------------
extern "C" void kernel_launch(void* const* d_in, const int* in_sizes, int n_in,
                              void* d_out, int out_size) {
    const float* inp;
    const float* tgt;
    if (in_sizes[0] > in_sizes[1]) { inp = (const float*)d_in[0]; tgt = (const float*)d_in[1]; }
    else                           { inp = (const float*)d_in[1]; tgt = (const float*)d_in[0]; }
    float* out = (float*)d_out;

    k_init  <<<272, 256>>>();
    k_build <<<1, 128>>>(tgt);
    k_scan  <<<SCAN_BLOCKS, SCAN_THREADS>>>(inp);
    k_masked<<<32, 256>>>(inp);
    k_final <<<1, SCAN_BLOCKS>>>(out);
}